// round 4
// baseline (speedup 1.0000x reference)
#include <cuda_runtime.h>
#include <cuda_bf16.h>

#define N_NODES 100000
#define N_EDGES 1600000
#define F_IN    165
#define F_HID   128
#define SCAN_CHUNK 1024
#define SCAN_NB ((N_NODES + SCAN_CHUNK - 1) / SCAN_CHUNK)   // 98

// ---- device scratch (allocation-free rule) ----
__device__ __align__(16) float g_h[N_NODES * F_HID];   // x @ W1
__device__ float g_dinv[N_NODES];
__device__ int   g_deg[N_NODES];
__device__ int   g_cursor[N_NODES];
__device__ int   g_rowstart[N_NODES + 1];
__device__ int   g_bsum[SCAN_NB];
__device__ int   g_src32[N_EDGES];
__device__ int   g_csr_src[N_EDGES];
__device__ float g_z[N_NODES];     // relu(agg+b1) . W4
__device__ float g_zd[N_NODES];    // z * dinv
__device__ int   g_is64;

__device__ __forceinline__ int clampN(int v) {
    return min(max(v, 0), N_NODES - 1);
}

// ---------------------------------------------------------------------------
// init (+ dtype detect: int64 ids < 100000 -> every odd 32-bit word is 0)
// ---------------------------------------------------------------------------
__global__ void k_init(const int* __restrict__ ei32) {
    int i = blockIdx.x * blockDim.x + threadIdx.x;
    if (i < N_NODES) { g_deg[i] = 0; g_cursor[i] = 0; }
    if (i == 0) {
        int z = 0;
        for (int k = 0; k < 16; k++) z |= ei32[2 * k + 1];
        g_is64 = (z == 0) ? 1 : 0;
    }
}

// degree count + dtype-aware conversion of src to int32
__global__ void k_deg(const void* __restrict__ eiv) {
    const int is64 = g_is64;
    const long long* e64 = (const long long*)eiv;
    const int*       e32 = (const int*)eiv;
    int stride = gridDim.x * blockDim.x;
    for (int e = blockIdx.x * blockDim.x + threadIdx.x; e < N_EDGES; e += stride) {
        int s, d;
        if (is64) { s = (int)e64[e]; d = (int)e64[N_EDGES + e]; }
        else      { s = e32[e];      d = e32[N_EDGES + e]; }
        g_src32[e] = clampN(s);
        atomicAdd(&g_deg[clampN(d)], 1);
    }
}

// ---- exclusive scan of deg -> rowstart (+ dinv fused) ----
__global__ __launch_bounds__(SCAN_CHUNK) void k_scan1() {
    __shared__ int sm[SCAN_CHUNK];
    int tid = threadIdx.x;
    int i = blockIdx.x * SCAN_CHUNK + tid;
    int v = (i < N_NODES) ? g_deg[i] : 0;
    if (i < N_NODES) g_dinv[i] = rsqrtf((float)(v + 1));   // +1: self loop
    sm[tid] = v;
    __syncthreads();
    for (int off = 1; off < SCAN_CHUNK; off <<= 1) {
        int t = (tid >= off) ? sm[tid - off] : 0;
        __syncthreads();
        sm[tid] += t;
        __syncthreads();
    }
    if (i < N_NODES) g_rowstart[i] = sm[tid] - v;     // exclusive
    if (tid == SCAN_CHUNK - 1) g_bsum[blockIdx.x] = sm[tid];
}

__global__ void k_scan2() {
    if (threadIdx.x == 0 && blockIdx.x == 0) {
        int run = 0;
        for (int b = 0; b < SCAN_NB; b++) {
            int t = g_bsum[b];
            g_bsum[b] = run;
            run += t;
        }
    }
}

__global__ void k_scan3() {
    int i = blockIdx.x * blockDim.x + threadIdx.x;
    if (i < N_NODES) g_rowstart[i] += g_bsum[i / SCAN_CHUNK];
    if (i == 0) g_rowstart[N_NODES] = N_EDGES;
}

// CSR fill (int atomics on cursors only)
__global__ void k_fill(const void* __restrict__ eiv) {
    const int is64 = g_is64;
    const long long* e64 = (const long long*)eiv;
    const int*       e32 = (const int*)eiv;
    int stride = gridDim.x * blockDim.x;
    for (int e = blockIdx.x * blockDim.x + threadIdx.x; e < N_EDGES; e += stride) {
        int d = is64 ? (int)e64[N_EDGES + e] : e32[N_EDGES + e];
        d = clampN(d);
        int pos = g_rowstart[d] + atomicAdd(&g_cursor[d], 1);
        g_csr_src[pos] = g_src32[e];
    }
}

// ---------------------------------------------------------------------------
// GEMM via packed fma.rn.f32x2: g_h = x[N,165] @ W1[165,128]
// tile 128x128, K chunk 15 (165 = 11*15), 256 thr, 8x8 per-thread tile
// ---------------------------------------------------------------------------
#define BM 128
#define BK 15

__device__ __forceinline__ void ffma2(unsigned long long& d,
                                      unsigned long long a,
                                      unsigned long long b) {
    asm("fma.rn.f32x2 %0, %1, %2, %0;" : "+l"(d) : "l"(a), "l"(b));
}

__device__ __forceinline__ unsigned long long pack2(float v) {
    unsigned long long p;
    asm("mov.b64 %0, {%1, %1};" : "=l"(p) : "f"(v));
    return p;
}

__global__ __launch_bounds__(256) void k_gemm1(const float* __restrict__ x,
                                               const float* __restrict__ W1) {
    __shared__ unsigned long long xs2[BM][BK + 1];  // duplicated (v,v) pairs
    __shared__ float ws[BK][F_HID];

    int t    = threadIdx.x;
    int row0 = blockIdx.x * BM;
    int trg  = t >> 4;     // rows trg*8 .. trg*8+7
    int tcg  = t & 15;     // cols tcg*8 .. tcg*8+7

    unsigned long long acc[8][4];
#pragma unroll
    for (int i = 0; i < 8; i++)
#pragma unroll
        for (int j = 0; j < 4; j++) acc[i][j] = 0ULL;

    for (int c = 0; c < 11; c++) {
        int k0 = c * BK;
        // load x tile (duplicate each scalar into a packed pair)
        for (int idx = t; idx < BM * BK; idx += 256) {
            int r  = idx / BK;
            int kk = idx % BK;
            int row = row0 + r;
            float v = (row < N_NODES) ? x[row * F_IN + k0 + kk] : 0.f;
            xs2[r][kk] = pack2(v);
        }
        // load W tile (coalesced)
        for (int idx = t; idx < BK * F_HID; idx += 256) {
            int kk = idx >> 7;
            int cc = idx & 127;
            ws[kk][cc] = W1[(k0 + kk) * F_HID + cc];
        }
        __syncthreads();

#pragma unroll
        for (int kk = 0; kk < BK; kk++) {
            unsigned long long a[8];
#pragma unroll
            for (int i = 0; i < 8; i++) a[i] = xs2[trg * 8 + i][kk];
            const ulonglong2* bp =
                reinterpret_cast<const ulonglong2*>(&ws[kk][tcg * 8]);
            ulonglong2 b01 = bp[0];
            ulonglong2 b23 = bp[1];
#pragma unroll
            for (int i = 0; i < 8; i++) {
                ffma2(acc[i][0], a[i], b01.x);
                ffma2(acc[i][1], a[i], b01.y);
                ffma2(acc[i][2], a[i], b23.x);
                ffma2(acc[i][3], a[i], b23.y);
            }
        }
        __syncthreads();
    }

#pragma unroll
    for (int i = 0; i < 8; i++) {
        int row = row0 + trg * 8 + i;
        if (row < N_NODES) {
            ulonglong2 s0, s1;
            s0.x = acc[i][0]; s0.y = acc[i][1];
            s1.x = acc[i][2]; s1.y = acc[i][3];
            *reinterpret_cast<ulonglong2*>(&g_h[row * F_HID + tcg * 8])     = s0;
            *reinterpret_cast<ulonglong2*>(&g_h[row * F_HID + tcg * 8 + 4]) = s1;
        }
    }
}

// ---------------------------------------------------------------------------
// Fused layer-1 aggregate + bias + ReLU + dot(W4): warp per dst node.
// ---------------------------------------------------------------------------
__global__ __launch_bounds__(256) void k_agg1(const float* __restrict__ b1,
                                              const float* __restrict__ W4) {
    int node = (blockIdx.x * blockDim.x + threadIdx.x) >> 5;
    int lane = threadIdx.x & 31;
    if (node >= N_NODES) return;

    int e0 = g_rowstart[node];
    int e1 = g_rowstart[node + 1];

    float4 acc = make_float4(0.f, 0.f, 0.f, 0.f);
    for (int base = e0; base < e1; base += 32) {
        int n = min(32, e1 - base);
        int s = 0; float dv = 0.f;
        if (base + lane < e1) {
            s  = g_csr_src[base + lane];
            dv = g_dinv[s];
        }
#pragma unroll 4
        for (int j = 0; j < n; j++) {
            int   sj = __shfl_sync(0xFFFFFFFFu, s,  j);
            float wj = __shfl_sync(0xFFFFFFFFu, dv, j);
            float4 hv = *reinterpret_cast<const float4*>(&g_h[sj * F_HID + lane * 4]);
            acc.x = fmaf(wj, hv.x, acc.x);
            acc.y = fmaf(wj, hv.y, acc.y);
            acc.z = fmaf(wj, hv.z, acc.z);
            acc.w = fmaf(wj, hv.w, acc.w);
        }
    }

    float dd = g_dinv[node];
    float self = dd * dd;
    float4 hv = *reinterpret_cast<const float4*>(&g_h[node * F_HID + lane * 4]);
    float4 bb = reinterpret_cast<const float4*>(b1)[lane];
    float4 ww = reinterpret_cast<const float4*>(W4)[lane];

    float r0 = fmaxf(fmaf(dd, acc.x, fmaf(self, hv.x, bb.x)), 0.f);
    float r1 = fmaxf(fmaf(dd, acc.y, fmaf(self, hv.y, bb.y)), 0.f);
    float r2 = fmaxf(fmaf(dd, acc.z, fmaf(self, hv.z, bb.z)), 0.f);
    float r3 = fmaxf(fmaf(dd, acc.w, fmaf(self, hv.w, bb.w)), 0.f);

    float dot = r0 * ww.x + r1 * ww.y + r2 * ww.z + r3 * ww.w;
#pragma unroll
    for (int o = 16; o > 0; o >>= 1)
        dot += __shfl_down_sync(0xFFFFFFFFu, dot, o);
    if (lane == 0) {
        g_z[node]  = dot;
        g_zd[node] = dot * dd;
    }
}

// ---------------------------------------------------------------------------
// Fused layer-2 gather + sigmoid: thread per node.
// ---------------------------------------------------------------------------
__global__ void k_out2(float* __restrict__ out, const float* __restrict__ b4) {
    int i = blockIdx.x * blockDim.x + threadIdx.x;
    if (i >= N_NODES) return;
    int e0 = g_rowstart[i];
    int e1 = g_rowstart[i + 1];
    float a = 0.f;
    for (int e = e0; e < e1; e++)
        a += g_zd[g_csr_src[e]];
    float dd = g_dinv[i];
    float v = fmaf(dd, a, dd * dd * g_z[i]) + b4[0];
    out[i] = 1.f / (1.f + expf(-v));
}

// ---------------------------------------------------------------------------
extern "C" void kernel_launch(void* const* d_in, const int* in_sizes, int n_in,
                              void* d_out, int out_size) {
    const float* x  = (const float*)d_in[0];
    const void*  ei = d_in[1];
    const float* W1 = (const float*)d_in[2];
    const float* b1 = (const float*)d_in[3];
    const float* W4 = (const float*)d_in[4];
    const float* b4 = (const float*)d_in[5];
    float* out = (float*)d_out;

    // launch order chosen so ncu's `-s 5 -c 1` profiles k_gemm1 (launch #6)
    k_init<<<(N_NODES + 255) / 256, 256>>>((const int*)ei);
    k_deg<<<2048, 256>>>(ei);
    k_scan1<<<SCAN_NB, SCAN_CHUNK>>>();
    k_scan2<<<1, 32>>>();
    k_scan3<<<(N_NODES + 255) / 256, 256>>>();
    k_gemm1<<<(N_NODES + BM - 1) / BM, 256>>>(x, W1);
    k_fill<<<2048, 256>>>(ei);
    k_agg1<<<(N_NODES * 32 + 255) / 256, 256>>>(b1, W4);
    k_out2<<<(N_NODES + 255) / 256, 256>>>(out, b4);
}

// round 5
// speedup vs baseline: 1.0629x; 1.0629x over previous
#include <cuda_runtime.h>
#include <cuda_bf16.h>

#define N_NODES 100000
#define N_EDGES 1600000
#define F_IN    165
#define F_HID   128
#define SCAN_CHUNK 1024
#define SCAN_NB ((N_NODES + SCAN_CHUNK - 1) / SCAN_CHUNK)   // 98

// ---- device scratch (allocation-free rule) ----
__device__ __align__(16) float g_h[N_NODES * F_HID];   // x @ W1
__device__ float g_dinv[N_NODES];
__device__ int   g_deg[N_NODES];
__device__ int   g_cursor[N_NODES];
__device__ int   g_rowstart[N_NODES + 1];
__device__ int   g_bsum[SCAN_NB];
__device__ int   g_src32[N_EDGES];
__device__ int   g_csr_src[N_EDGES];
__device__ float g_z[N_NODES];     // relu(agg+b1) . W4
__device__ float g_zd[N_NODES];    // z * dinv
__device__ int   g_is64;

__device__ __forceinline__ int clampN(int v) {
    return min(max(v, 0), N_NODES - 1);
}

// ---------------------------------------------------------------------------
// init (+ dtype detect: int64 ids < 100000 -> every odd 32-bit word is 0)
// ---------------------------------------------------------------------------
__global__ void k_init(const int* __restrict__ ei32) {
    int i = blockIdx.x * blockDim.x + threadIdx.x;
    if (i < N_NODES) { g_deg[i] = 0; g_cursor[i] = 0; }
    if (i == 0) {
        int z = 0;
        for (int k = 0; k < 16; k++) z |= ei32[2 * k + 1];
        g_is64 = (z == 0) ? 1 : 0;
    }
}

// degree count + dtype-aware conversion of src to int32
__global__ void k_deg(const void* __restrict__ eiv) {
    const int is64 = g_is64;
    const long long* e64 = (const long long*)eiv;
    const int*       e32 = (const int*)eiv;
    int stride = gridDim.x * blockDim.x;
    for (int e = blockIdx.x * blockDim.x + threadIdx.x; e < N_EDGES; e += stride) {
        int s, d;
        if (is64) { s = (int)e64[e]; d = (int)e64[N_EDGES + e]; }
        else      { s = e32[e];      d = e32[N_EDGES + e]; }
        g_src32[e] = clampN(s);
        atomicAdd(&g_deg[clampN(d)], 1);
    }
}

// ---- exclusive scan of deg -> rowstart (+ dinv fused) ----
__global__ __launch_bounds__(SCAN_CHUNK) void k_scan1() {
    __shared__ int sm[SCAN_CHUNK];
    int tid = threadIdx.x;
    int i = blockIdx.x * SCAN_CHUNK + tid;
    int v = (i < N_NODES) ? g_deg[i] : 0;
    if (i < N_NODES) g_dinv[i] = rsqrtf((float)(v + 1));   // +1: self loop
    sm[tid] = v;
    __syncthreads();
    for (int off = 1; off < SCAN_CHUNK; off <<= 1) {
        int t = (tid >= off) ? sm[tid - off] : 0;
        __syncthreads();
        sm[tid] += t;
        __syncthreads();
    }
    if (i < N_NODES) g_rowstart[i] = sm[tid] - v;     // exclusive
    if (tid == SCAN_CHUNK - 1) g_bsum[blockIdx.x] = sm[tid];
}

// single-warp scan of the 98 block sums
__global__ void k_scan2() {
    int lane = threadIdx.x & 31;
    int carry = 0;
    for (int b = 0; b < SCAN_NB; b += 32) {
        int idx = b + lane;
        int orig = (idx < SCAN_NB) ? g_bsum[idx] : 0;
        int v = orig;
#pragma unroll
        for (int off = 1; off < 32; off <<= 1) {
            int t = __shfl_up_sync(0xFFFFFFFFu, v, off);
            if (lane >= off) v += t;
        }
        if (idx < SCAN_NB) g_bsum[idx] = carry + v - orig;   // exclusive
        carry += __shfl_sync(0xFFFFFFFFu, v, 31);
    }
}

__global__ void k_scan3() {
    int i = blockIdx.x * blockDim.x + threadIdx.x;
    if (i < N_NODES) g_rowstart[i] += g_bsum[i / SCAN_CHUNK];
    if (i == 0) g_rowstart[N_NODES] = N_EDGES;
}

// CSR fill (int atomics on cursors only)
__global__ void k_fill(const void* __restrict__ eiv) {
    const int is64 = g_is64;
    const long long* e64 = (const long long*)eiv;
    const int*       e32 = (const int*)eiv;
    int stride = gridDim.x * blockDim.x;
    for (int e = blockIdx.x * blockDim.x + threadIdx.x; e < N_EDGES; e += stride) {
        int d = is64 ? (int)e64[N_EDGES + e] : e32[N_EDGES + e];
        d = clampN(d);
        int pos = g_rowstart[d] + atomicAdd(&g_cursor[d], 1);
        g_csr_src[pos] = g_src32[e];
    }
}

// ---------------------------------------------------------------------------
// GEMM via packed fma.rn.f32x2: g_h = x[N,165] @ W1[165,128]
// tile 128x128, K chunk 15 (165 = 11*15), 256 thr, 8x8 per-thread tile
// ---------------------------------------------------------------------------
#define BM 128
#define BK 15

__device__ __forceinline__ void ffma2(unsigned long long& d,
                                      unsigned long long a,
                                      unsigned long long b) {
    asm("fma.rn.f32x2 %0, %1, %2, %0;" : "+l"(d) : "l"(a), "l"(b));
}

__device__ __forceinline__ unsigned long long pack2(float v) {
    unsigned long long p;
    asm("mov.b64 %0, {%1, %1};" : "=l"(p) : "f"(v));
    return p;
}

__global__ __launch_bounds__(256) void k_gemm1(const float* __restrict__ x,
                                               const float* __restrict__ W1) {
    __shared__ unsigned long long xs2[BM][BK + 1];  // duplicated (v,v) pairs
    __shared__ float ws[BK][F_HID];

    int t    = threadIdx.x;
    int row0 = blockIdx.x * BM;
    int trg  = t >> 4;     // rows trg*8 .. trg*8+7
    int tcg  = t & 15;     // cols tcg*8 .. tcg*8+7

    unsigned long long acc[8][4];
#pragma unroll
    for (int i = 0; i < 8; i++)
#pragma unroll
        for (int j = 0; j < 4; j++) acc[i][j] = 0ULL;

    for (int c = 0; c < 11; c++) {
        int k0 = c * BK;
        for (int idx = t; idx < BM * BK; idx += 256) {
            int r  = idx / BK;
            int kk = idx % BK;
            int row = row0 + r;
            float v = (row < N_NODES) ? x[row * F_IN + k0 + kk] : 0.f;
            xs2[r][kk] = pack2(v);
        }
        for (int idx = t; idx < BK * F_HID; idx += 256) {
            int kk = idx >> 7;
            int cc = idx & 127;
            ws[kk][cc] = W1[(k0 + kk) * F_HID + cc];
        }
        __syncthreads();

#pragma unroll
        for (int kk = 0; kk < BK; kk++) {
            unsigned long long a[8];
#pragma unroll
            for (int i = 0; i < 8; i++) a[i] = xs2[trg * 8 + i][kk];
            const ulonglong2* bp =
                reinterpret_cast<const ulonglong2*>(&ws[kk][tcg * 8]);
            ulonglong2 b01 = bp[0];
            ulonglong2 b23 = bp[1];
#pragma unroll
            for (int i = 0; i < 8; i++) {
                ffma2(acc[i][0], a[i], b01.x);
                ffma2(acc[i][1], a[i], b01.y);
                ffma2(acc[i][2], a[i], b23.x);
                ffma2(acc[i][3], a[i], b23.y);
            }
        }
        __syncthreads();
    }

#pragma unroll
    for (int i = 0; i < 8; i++) {
        int row = row0 + trg * 8 + i;
        if (row < N_NODES) {
            ulonglong2 s0, s1;
            s0.x = acc[i][0]; s0.y = acc[i][1];
            s1.x = acc[i][2]; s1.y = acc[i][3];
            *reinterpret_cast<ulonglong2*>(&g_h[row * F_HID + tcg * 8])     = s0;
            *reinterpret_cast<ulonglong2*>(&g_h[row * F_HID + tcg * 8 + 4]) = s1;
        }
    }
}

// ---------------------------------------------------------------------------
// Fused layer-1 aggregate + bias + ReLU + dot(W4): warp per dst node.
// ---------------------------------------------------------------------------
__global__ __launch_bounds__(256) void k_agg1(const float* __restrict__ b1,
                                              const float* __restrict__ W4) {
    int node = (blockIdx.x * blockDim.x + threadIdx.x) >> 5;
    int lane = threadIdx.x & 31;
    if (node >= N_NODES) return;

    int e0 = g_rowstart[node];
    int e1 = g_rowstart[node + 1];

    float4 acc = make_float4(0.f, 0.f, 0.f, 0.f);
    for (int base = e0; base < e1; base += 32) {
        int n = min(32, e1 - base);
        int s = 0; float dv = 0.f;
        if (base + lane < e1) {
            s  = g_csr_src[base + lane];
            dv = g_dinv[s];
        }
#pragma unroll 4
        for (int j = 0; j < n; j++) {
            int   sj = __shfl_sync(0xFFFFFFFFu, s,  j);
            float wj = __shfl_sync(0xFFFFFFFFu, dv, j);
            float4 hv = *reinterpret_cast<const float4*>(&g_h[sj * F_HID + lane * 4]);
            acc.x = fmaf(wj, hv.x, acc.x);
            acc.y = fmaf(wj, hv.y, acc.y);
            acc.z = fmaf(wj, hv.z, acc.z);
            acc.w = fmaf(wj, hv.w, acc.w);
        }
    }

    float dd = g_dinv[node];
    float self = dd * dd;
    float4 hv = *reinterpret_cast<const float4*>(&g_h[node * F_HID + lane * 4]);
    float4 bb = reinterpret_cast<const float4*>(b1)[lane];
    float4 ww = reinterpret_cast<const float4*>(W4)[lane];

    float r0 = fmaxf(fmaf(dd, acc.x, fmaf(self, hv.x, bb.x)), 0.f);
    float r1 = fmaxf(fmaf(dd, acc.y, fmaf(self, hv.y, bb.y)), 0.f);
    float r2 = fmaxf(fmaf(dd, acc.z, fmaf(self, hv.z, bb.z)), 0.f);
    float r3 = fmaxf(fmaf(dd, acc.w, fmaf(self, hv.w, bb.w)), 0.f);

    float dot = r0 * ww.x + r1 * ww.y + r2 * ww.z + r3 * ww.w;
#pragma unroll
    for (int o = 16; o > 0; o >>= 1)
        dot += __shfl_down_sync(0xFFFFFFFFu, dot, o);
    if (lane == 0) {
        g_z[node]  = dot;
        g_zd[node] = dot * dd;
    }
}

// ---------------------------------------------------------------------------
// Fused layer-2 gather + sigmoid: thread per node.
// ---------------------------------------------------------------------------
__global__ void k_out2(float* __restrict__ out, const float* __restrict__ b4) {
    int i = blockIdx.x * blockDim.x + threadIdx.x;
    if (i >= N_NODES) return;
    int e0 = g_rowstart[i];
    int e1 = g_rowstart[i + 1];
    float a = 0.f;
    for (int e = e0; e < e1; e++)
        a += g_zd[g_csr_src[e]];
    float dd = g_dinv[i];
    float v = fmaf(dd, a, dd * dd * g_z[i]) + b4[0];
    out[i] = 1.f / (1.f + expf(-v));
}

// ---------------------------------------------------------------------------
extern "C" void kernel_launch(void* const* d_in, const int* in_sizes, int n_in,
                              void* d_out, int out_size) {
    const float* x  = (const float*)d_in[0];
    const void*  ei = d_in[1];
    const float* W1 = (const float*)d_in[2];
    const float* b1 = (const float*)d_in[3];
    const float* W4 = (const float*)d_in[4];
    const float* b4 = (const float*)d_in[5];
    float* out = (float*)d_out;

    // side stream + fork/join events, created once on the (non-captured)
    // correctness call; reused identically on every call thereafter.
    static cudaStream_t s_side = nullptr;
    static cudaEvent_t  ev_fork = nullptr, ev_join = nullptr;
    if (s_side == nullptr) {
        cudaStreamCreateWithFlags(&s_side, cudaStreamNonBlocking);
        cudaEventCreateWithFlags(&ev_fork, cudaEventDisableTiming);
        cudaEventCreateWithFlags(&ev_join, cudaEventDisableTiming);
    }

    // fork: GEMM (x,W1 only) runs concurrently with the CSR build chain
    cudaEventRecord(ev_fork, 0);
    cudaStreamWaitEvent(s_side, ev_fork, 0);
    k_gemm1<<<(N_NODES + BM - 1) / BM, 256, 0, s_side>>>(x, W1);
    cudaEventRecord(ev_join, s_side);

    // CSR build chain on the main stream
    k_init<<<(N_NODES + 255) / 256, 256>>>((const int*)ei);
    k_deg<<<2048, 256>>>(ei);
    k_scan1<<<SCAN_NB, SCAN_CHUNK>>>();
    k_scan2<<<1, 32>>>();
    k_scan3<<<(N_NODES + 255) / 256, 256>>>();
    k_fill<<<2048, 256>>>(ei);

    // join: agg needs both g_h (side) and CSR (main)
    cudaStreamWaitEvent(0, ev_join, 0);
    k_agg1<<<(N_NODES * 32 + 255) / 256, 256>>>(b1, W4);
    k_out2<<<(N_NODES + 255) / 256, 256>>>(out, b4);
}

// round 6
// speedup vs baseline: 1.5735x; 1.4804x over previous
#include <cuda_runtime.h>
#include <cuda_bf16.h>

#define N_NODES 100000
#define N_EDGES 1600000
#define F_IN    165
#define F_HID   128
#define SCAN_CHUNK 1024
#define SCAN_NB ((N_NODES + SCAN_CHUNK - 1) / SCAN_CHUNK)   // 98

// ---- device scratch (allocation-free rule) ----
__device__ __align__(16) __nv_bfloat16 g_hb[N_NODES * F_HID];  // bf16(x @ W1)
__device__ float g_dinv[N_NODES];
__device__ int   g_deg[N_NODES];
__device__ int   g_cursor[N_NODES];
__device__ int   g_rowstart[N_NODES + 1];
__device__ int   g_bsum[SCAN_NB];
__device__ int   g_src32[N_EDGES];
__device__ int   g_csr_src[N_EDGES];
__device__ float g_z[N_NODES];     // relu(agg+b1) . W4
__device__ float g_zd[N_NODES];    // z * dinv
__device__ int   g_is64;

__device__ __forceinline__ int clampN(int v) {
    return min(max(v, 0), N_NODES - 1);
}

// ---------------------------------------------------------------------------
// init (+ dtype detect: int64 ids < 100000 -> every odd 32-bit word is 0)
// ---------------------------------------------------------------------------
__global__ void k_init(const int* __restrict__ ei32) {
    int i = blockIdx.x * blockDim.x + threadIdx.x;
    if (i < N_NODES) { g_deg[i] = 0; g_cursor[i] = 0; }
    if (i == 0) {
        int z = 0;
        for (int k = 0; k < 16; k++) z |= ei32[2 * k + 1];
        g_is64 = (z == 0) ? 1 : 0;
    }
}

// degree count + dtype-aware conversion of src to int32
__global__ void k_deg(const void* __restrict__ eiv) {
    const int is64 = g_is64;
    const long long* e64 = (const long long*)eiv;
    const int*       e32 = (const int*)eiv;
    int stride = gridDim.x * blockDim.x;
    for (int e = blockIdx.x * blockDim.x + threadIdx.x; e < N_EDGES; e += stride) {
        int s, d;
        if (is64) { s = (int)e64[e]; d = (int)e64[N_EDGES + e]; }
        else      { s = e32[e];      d = e32[N_EDGES + e]; }
        g_src32[e] = clampN(s);
        atomicAdd(&g_deg[clampN(d)], 1);
    }
}

// ---- exclusive scan of deg -> rowstart (+ dinv fused) ----
__global__ __launch_bounds__(SCAN_CHUNK) void k_scan1() {
    __shared__ int sm[SCAN_CHUNK];
    int tid = threadIdx.x;
    int i = blockIdx.x * SCAN_CHUNK + tid;
    int v = (i < N_NODES) ? g_deg[i] : 0;
    if (i < N_NODES) g_dinv[i] = rsqrtf((float)(v + 1));   // +1: self loop
    sm[tid] = v;
    __syncthreads();
    for (int off = 1; off < SCAN_CHUNK; off <<= 1) {
        int t = (tid >= off) ? sm[tid - off] : 0;
        __syncthreads();
        sm[tid] += t;
        __syncthreads();
    }
    if (i < N_NODES) g_rowstart[i] = sm[tid] - v;     // exclusive
    if (tid == SCAN_CHUNK - 1) g_bsum[blockIdx.x] = sm[tid];
}

// single-warp scan of the 98 block sums
__global__ void k_scan2() {
    int lane = threadIdx.x & 31;
    int carry = 0;
    for (int b = 0; b < SCAN_NB; b += 32) {
        int idx = b + lane;
        int orig = (idx < SCAN_NB) ? g_bsum[idx] : 0;
        int v = orig;
#pragma unroll
        for (int off = 1; off < 32; off <<= 1) {
            int t = __shfl_up_sync(0xFFFFFFFFu, v, off);
            if (lane >= off) v += t;
        }
        if (idx < SCAN_NB) g_bsum[idx] = carry + v - orig;   // exclusive
        carry += __shfl_sync(0xFFFFFFFFu, v, 31);
    }
}

__global__ void k_scan3() {
    int i = blockIdx.x * blockDim.x + threadIdx.x;
    if (i < N_NODES) g_rowstart[i] += g_bsum[i / SCAN_CHUNK];
    if (i == 0) g_rowstart[N_NODES] = N_EDGES;
}

// CSR fill (int atomics on cursors only)
__global__ void k_fill(const void* __restrict__ eiv) {
    const int is64 = g_is64;
    const long long* e64 = (const long long*)eiv;
    const int*       e32 = (const int*)eiv;
    int stride = gridDim.x * blockDim.x;
    for (int e = blockIdx.x * blockDim.x + threadIdx.x; e < N_EDGES; e += stride) {
        int d = is64 ? (int)e64[N_EDGES + e] : e32[N_EDGES + e];
        d = clampN(d);
        int pos = g_rowstart[d] + atomicAdd(&g_cursor[d], 1);
        g_csr_src[pos] = g_src32[e];
    }
}

// ---------------------------------------------------------------------------
// GEMM via packed fma.rn.f32x2: h = x[N,165] @ W1[165,128] -> bf16 store
// tile 128x128, K chunk 15 (165 = 11*15), 256 thr, 8x8 per-thread tile
// ---------------------------------------------------------------------------
#define BM 128
#define BK 15

__device__ __forceinline__ void ffma2(unsigned long long& d,
                                      unsigned long long a,
                                      unsigned long long b) {
    asm("fma.rn.f32x2 %0, %1, %2, %0;" : "+l"(d) : "l"(a), "l"(b));
}

__device__ __forceinline__ unsigned long long pack2(float v) {
    unsigned long long p;
    asm("mov.b64 %0, {%1, %1};" : "=l"(p) : "f"(v));
    return p;
}

__device__ __forceinline__ float2 unpack2(unsigned long long p) {
    float2 f;
    asm("mov.b64 {%0, %1}, %2;" : "=f"(f.x), "=f"(f.y) : "l"(p));
    return f;
}

__global__ __launch_bounds__(256) void k_gemm1(const float* __restrict__ x,
                                               const float* __restrict__ W1) {
    __shared__ unsigned long long xs2[BM][BK + 1];  // duplicated (v,v) pairs
    __shared__ float ws[BK][F_HID];

    int t    = threadIdx.x;
    int row0 = blockIdx.x * BM;
    int trg  = t >> 4;     // rows trg*8 .. trg*8+7
    int tcg  = t & 15;     // cols tcg*8 .. tcg*8+7

    unsigned long long acc[8][4];
#pragma unroll
    for (int i = 0; i < 8; i++)
#pragma unroll
        for (int j = 0; j < 4; j++) acc[i][j] = 0ULL;

    for (int c = 0; c < 11; c++) {
        int k0 = c * BK;
        for (int idx = t; idx < BM * BK; idx += 256) {
            int r  = idx / BK;
            int kk = idx % BK;
            int row = row0 + r;
            float v = (row < N_NODES) ? x[row * F_IN + k0 + kk] : 0.f;
            xs2[r][kk] = pack2(v);
        }
        for (int idx = t; idx < BK * F_HID; idx += 256) {
            int kk = idx >> 7;
            int cc = idx & 127;
            ws[kk][cc] = W1[(k0 + kk) * F_HID + cc];
        }
        __syncthreads();

#pragma unroll
        for (int kk = 0; kk < BK; kk++) {
            unsigned long long a[8];
#pragma unroll
            for (int i = 0; i < 8; i++) a[i] = xs2[trg * 8 + i][kk];
            const ulonglong2* bp =
                reinterpret_cast<const ulonglong2*>(&ws[kk][tcg * 8]);
            ulonglong2 b01 = bp[0];
            ulonglong2 b23 = bp[1];
#pragma unroll
            for (int i = 0; i < 8; i++) {
                ffma2(acc[i][0], a[i], b01.x);
                ffma2(acc[i][1], a[i], b01.y);
                ffma2(acc[i][2], a[i], b23.x);
                ffma2(acc[i][3], a[i], b23.y);
            }
        }
        __syncthreads();
    }

#pragma unroll
    for (int i = 0; i < 8; i++) {
        int row = row0 + trg * 8 + i;
        if (row < N_NODES) {
            __nv_bfloat162 h0 = __float22bfloat162_rn(unpack2(acc[i][0]));
            __nv_bfloat162 h1 = __float22bfloat162_rn(unpack2(acc[i][1]));
            __nv_bfloat162 h2 = __float22bfloat162_rn(unpack2(acc[i][2]));
            __nv_bfloat162 h3 = __float22bfloat162_rn(unpack2(acc[i][3]));
            uint4 o;
            o.x = *reinterpret_cast<unsigned*>(&h0);
            o.y = *reinterpret_cast<unsigned*>(&h1);
            o.z = *reinterpret_cast<unsigned*>(&h2);
            o.w = *reinterpret_cast<unsigned*>(&h3);
            *reinterpret_cast<uint4*>(&g_hb[row * F_HID + tcg * 8]) = o;
        }
    }
}

// ---------------------------------------------------------------------------
// Fused layer-1 aggregate + bias + ReLU + dot(W4): warp per dst node.
// bf16 h gather (8 B/lane/edge), fp32 accumulate.
// ---------------------------------------------------------------------------
__global__ __launch_bounds__(256) void k_agg1(const float* __restrict__ b1,
                                              const float* __restrict__ W4) {
    int node = (blockIdx.x * blockDim.x + threadIdx.x) >> 5;
    int lane = threadIdx.x & 31;
    if (node >= N_NODES) return;

    int e0 = g_rowstart[node];
    int e1 = g_rowstart[node + 1];

    float4 acc = make_float4(0.f, 0.f, 0.f, 0.f);
    for (int base = e0; base < e1; base += 32) {
        int n = min(32, e1 - base);
        int s = 0; float dv = 0.f;
        if (base + lane < e1) {
            s  = g_csr_src[base + lane];
            dv = g_dinv[s];
        }
#pragma unroll 4
        for (int j = 0; j < n; j++) {
            int   sj = __shfl_sync(0xFFFFFFFFu, s,  j);
            float wj = __shfl_sync(0xFFFFFFFFu, dv, j);
            uint2 hp = *reinterpret_cast<const uint2*>(&g_hb[sj * F_HID + lane * 4]);
            float2 f0 = __bfloat1622float2(*reinterpret_cast<__nv_bfloat162*>(&hp.x));
            float2 f1 = __bfloat1622float2(*reinterpret_cast<__nv_bfloat162*>(&hp.y));
            acc.x = fmaf(wj, f0.x, acc.x);
            acc.y = fmaf(wj, f0.y, acc.y);
            acc.z = fmaf(wj, f1.x, acc.z);
            acc.w = fmaf(wj, f1.y, acc.w);
        }
    }

    float dd = g_dinv[node];
    float self = dd * dd;
    uint2 hp = *reinterpret_cast<const uint2*>(&g_hb[node * F_HID + lane * 4]);
    float2 h0 = __bfloat1622float2(*reinterpret_cast<__nv_bfloat162*>(&hp.x));
    float2 h1 = __bfloat1622float2(*reinterpret_cast<__nv_bfloat162*>(&hp.y));
    float4 bb = reinterpret_cast<const float4*>(b1)[lane];
    float4 ww = reinterpret_cast<const float4*>(W4)[lane];

    float r0 = fmaxf(fmaf(dd, acc.x, fmaf(self, h0.x, bb.x)), 0.f);
    float r1 = fmaxf(fmaf(dd, acc.y, fmaf(self, h0.y, bb.y)), 0.f);
    float r2 = fmaxf(fmaf(dd, acc.z, fmaf(self, h1.x, bb.z)), 0.f);
    float r3 = fmaxf(fmaf(dd, acc.w, fmaf(self, h1.y, bb.w)), 0.f);

    float dot = r0 * ww.x + r1 * ww.y + r2 * ww.z + r3 * ww.w;
#pragma unroll
    for (int o = 16; o > 0; o >>= 1)
        dot += __shfl_down_sync(0xFFFFFFFFu, dot, o);
    if (lane == 0) {
        g_z[node]  = dot;
        g_zd[node] = dot * dd;
    }
}

// ---------------------------------------------------------------------------
// Fused layer-2 gather + sigmoid: thread per node.
// ---------------------------------------------------------------------------
__global__ void k_out2(float* __restrict__ out, const float* __restrict__ b4) {
    int i = blockIdx.x * blockDim.x + threadIdx.x;
    if (i >= N_NODES) return;
    int e0 = g_rowstart[i];
    int e1 = g_rowstart[i + 1];
    float a = 0.f;
    for (int e = e0; e < e1; e++)
        a += g_zd[g_csr_src[e]];
    float dd = g_dinv[i];
    float v = fmaf(dd, a, dd * dd * g_z[i]) + b4[0];
    out[i] = 1.f / (1.f + expf(-v));
}

// ---------------------------------------------------------------------------
extern "C" void kernel_launch(void* const* d_in, const int* in_sizes, int n_in,
                              void* d_out, int out_size) {
    const float* x  = (const float*)d_in[0];
    const void*  ei = d_in[1];
    const float* W1 = (const float*)d_in[2];
    const float* b1 = (const float*)d_in[3];
    const float* W4 = (const float*)d_in[4];
    const float* b4 = (const float*)d_in[5];
    float* out = (float*)d_out;

    static cudaStream_t s_side = nullptr;
    static cudaEvent_t  ev_fork = nullptr, ev_join = nullptr;
    if (s_side == nullptr) {
        cudaStreamCreateWithFlags(&s_side, cudaStreamNonBlocking);
        cudaEventCreateWithFlags(&ev_fork, cudaEventDisableTiming);
        cudaEventCreateWithFlags(&ev_join, cudaEventDisableTiming);
    }

    // fork: GEMM (x,W1 only) runs concurrently with the CSR build chain
    cudaEventRecord(ev_fork, 0);
    cudaStreamWaitEvent(s_side, ev_fork, 0);
    k_gemm1<<<(N_NODES + BM - 1) / BM, 256, 0, s_side>>>(x, W1);
    cudaEventRecord(ev_join, s_side);

    // CSR build chain on the main stream
    k_init<<<(N_NODES + 255) / 256, 256>>>((const int*)ei);
    k_deg<<<2048, 256>>>(ei);
    k_scan1<<<SCAN_NB, SCAN_CHUNK>>>();
    k_scan2<<<1, 32>>>();
    k_scan3<<<(N_NODES + 255) / 256, 256>>>();
    k_fill<<<2048, 256>>>(ei);

    // join: agg needs both g_hb (side) and CSR (main)
    cudaStreamWaitEvent(0, ev_join, 0);
    k_agg1<<<(N_NODES * 32 + 255) / 256, 256>>>(b1, W4);
    k_out2<<<(N_NODES + 255) / 256, 256>>>(out, b4);
}